// round 2
// baseline (speedup 1.0000x reference)
#include <cuda_runtime.h>
#include <math.h>

#define NB   16
#define CIN  256
#define COUT 256
#define NE   8
#define HH   64
#define WW   64
#define KWT  9          // 3x3

// ---------------- scratch (no allocations allowed) ----------------
__device__ float g_pooled[NB * CIN];
__device__ float g_routing[NB * NE];
__device__ float g_aggb[NB * COUT];
__device__ float g_aggw[(size_t)NB * COUT * CIN * KWT];   // 37.75 MB

// ---------------- stage 1: global average pool ----------------
// grid (CIN, NB), 256 threads; each block reduces one [H*W] plane.
__global__ void pool_kernel(const float* __restrict__ x) {
    int c = blockIdx.x, b = blockIdx.y;
    const float4* p = (const float4*)(x + ((size_t)b * CIN + c) * (HH * WW));
    float s = 0.f;
    for (int i = threadIdx.x; i < (HH * WW) / 4; i += 256) {
        float4 v = p[i];
        s += v.x + v.y + v.z + v.w;
    }
    __shared__ float red[8];
    #pragma unroll
    for (int o = 16; o > 0; o >>= 1) s += __shfl_xor_sync(0xFFFFFFFFu, s, o);
    if ((threadIdx.x & 31) == 0) red[threadIdx.x >> 5] = s;
    __syncthreads();
    if (threadIdx.x == 0) {
        float t = 0.f;
        #pragma unroll
        for (int i = 0; i < 8; i++) t += red[i];
        g_pooled[b * CIN + c] = t * (1.0f / (HH * WW));
    }
}

// ---------------- stage 2: routing (sigmoid) + aggregated bias ----------------
// grid NB, 256 threads.
__global__ void routing_kernel(const float* __restrict__ rw,
                               const float* __restrict__ rb,
                               const float* __restrict__ bias) {
    int b = blockIdx.x;
    __shared__ float sp[CIN];
    __shared__ float sr[NE];
    sp[threadIdx.x] = g_pooled[b * CIN + threadIdx.x];
    __syncthreads();
    int warp = threadIdx.x >> 5, lane = threadIdx.x & 31;
    if (warp < NE) {
        float s = 0.f;
        for (int c = lane; c < CIN; c += 32) s += sp[c] * rw[warp * CIN + c];
        #pragma unroll
        for (int o = 16; o > 0; o >>= 1) s += __shfl_xor_sync(0xFFFFFFFFu, s, o);
        if (lane == 0) {
            float z = s + rb[warp];
            sr[warp] = 1.0f / (1.0f + expf(-z));
        }
    }
    __syncthreads();
    if (threadIdx.x < NE) g_routing[b * NE + threadIdx.x] = sr[threadIdx.x];
    float a = 0.f;
    #pragma unroll
    for (int e = 0; e < NE; e++) a += sr[e] * bias[e * COUT + threadIdx.x];
    g_aggb[b * COUT + threadIdx.x] = a;
}

// ---------------- stage 3: per-sample aggregated weights ----------------
// Read each weight element ONCE (8 experts), broadcast to all 16 batches.
// total idx = COUT*CIN*9 = 589824; grid 2304 x 256 threads.
__global__ void aggw_kernel(const float* __restrict__ weight) {
    __shared__ float sr[NB * NE];
    if (threadIdx.x < NB * NE) sr[threadIdx.x] = g_routing[threadIdx.x];
    __syncthreads();
    size_t idx = (size_t)blockIdx.x * 256 + threadIdx.x;
    const size_t EW = (size_t)COUT * CIN * KWT;
    float wv[NE];
    #pragma unroll
    for (int e = 0; e < NE; e++) wv[e] = weight[(size_t)e * EW + idx];
    #pragma unroll
    for (int b = 0; b < NB; b++) {
        float a = 0.f;
        #pragma unroll
        for (int e = 0; e < NE; e++) a += sr[b * NE + e] * wv[e];
        g_aggw[(size_t)b * EW + idx] = a;
    }
}

// ---------------- stage 4: per-sample 3x3 conv (implicit GEMM, fp32) ----------------
// Block: batch b, 32 output channels, spatial tile 8 rows x 64 cols.
// Thread (256/block): 8 oc x 8 px register tile.
#define TOC 32
#define TR  8
#define CI  8
#define XSS 66   // x smem row stride (64 + 2 halo)
#define WSS 33   // weight smem oc stride (pad to kill bank conflicts)

__global__ __launch_bounds__(256, 2) void conv_kernel(const float* __restrict__ x,
                                                      float* __restrict__ out) {
    const int rt  = blockIdx.x;            // row tile 0..7
    const int ot  = blockIdx.y;            // oc tile  0..7
    const int b   = blockIdx.z;            // batch    0..15
    const int r0  = rt * TR;
    const int oc0 = ot * TOC;
    const int tid = threadIdx.x;
    const int ocg  = tid >> 6;             // 0..3  (warp-uniform)
    const int row  = (tid >> 3) & 7;       // 0..7
    const int colg = tid & 7;              // 0..7
    const int c0   = colg * 8;

    __shared__ float xs[CI * 10 * XSS];    // 5280 f = 21.1 KB
    __shared__ float ws[CI * KWT * WSS];   // 2376 f =  9.5 KB

    float acc[8][8];
    #pragma unroll
    for (int j = 0; j < 8; j++)
        #pragma unroll
        for (int p = 0; p < 8; p++) acc[j][p] = 0.f;

    const float* xb = x + (size_t)b * CIN * HH * WW;
    const float* wb = g_aggw + (size_t)b * COUT * CIN * KWT;

    for (int ci0 = 0; ci0 < CIN; ci0 += CI) {
        __syncthreads();
        // x tile: CI channels x 10 rows (halo) x 66 cols (halo), zero-padded.
        // One iteration handles one (ci, rr) smem row segment per thread-chunk.
        for (int i = tid; i < CI * 10 * XSS; i += 256) {
            int cc = i % XSS;
            int t  = i / XSS;
            int rr = t % 10;
            int ci = t / 10;
            int gr = r0 - 1 + rr;
            int gc = cc - 1;
            bool rowok = (unsigned)gr < HH;
            float v = 0.f;
            if (rowok && (unsigned)gc < WW)
                v = __ldg(&xb[((size_t)(ci0 + ci) * HH + gr) * WW + gc]);
            xs[(ci * 10 + rr) * XSS + cc] = v;
        }
        // weights: [oc][ci][3][3] -> ws[(ci*9+k)*33 + oc]   (coalesced gmem reads)
        for (int i = tid; i < TOC * (CI * KWT); i += 256) {
            int oc  = i / (CI * KWT);
            int cik = i % (CI * KWT);
            ws[cik * WSS + oc] =
                wb[(size_t)(oc0 + oc) * CIN * KWT + (size_t)(ci0) * KWT + cik];
        }
        __syncthreads();

        #pragma unroll
        for (int ci = 0; ci < CI; ci++) {
            #pragma unroll
            for (int dr = 0; dr < 3; dr++) {
                float xr[10];
                const float* xrow = &xs[(ci * 10 + row + dr) * XSS + c0];
                #pragma unroll
                for (int t = 0; t < 10; t++) xr[t] = xrow[t];
                #pragma unroll
                for (int dc = 0; dc < 3; dc++) {
                    const int kbase = (ci * KWT + dr * 3 + dc) * WSS + ocg * 8;
                    #pragma unroll
                    for (int j = 0; j < 8; j++) {
                        float wv = ws[kbase + j];   // warp-uniform broadcast
                        #pragma unroll
                        for (int p = 0; p < 8; p++)
                            acc[j][p] = fmaf(wv, xr[dc + p], acc[j][p]);
                    }
                }
            }
        }
    }

    // epilogue: + aggregated bias, vectorized store
    float* ob = out + (size_t)b * COUT * HH * WW;
    #pragma unroll
    for (int j = 0; j < 8; j++) {
        int oc = oc0 + ocg * 8 + j;
        float bb = g_aggb[b * COUT + oc];
        float4 v0 = make_float4(acc[j][0] + bb, acc[j][1] + bb,
                                acc[j][2] + bb, acc[j][3] + bb);
        float4 v1 = make_float4(acc[j][4] + bb, acc[j][5] + bb,
                                acc[j][6] + bb, acc[j][7] + bb);
        float4* po = (float4*)&ob[((size_t)oc * HH + (r0 + row)) * WW + c0];
        po[0] = v0;
        po[1] = v1;
    }
}

// ---------------- launch ----------------
extern "C" void kernel_launch(void* const* d_in, const int* in_sizes, int n_in,
                              void* d_out, int out_size) {
    const float* x    = (const float*)d_in[0];   // [16,256,64,64]
    const float* wgt  = (const float*)d_in[1];   // [8,256,256,3,3]
    const float* bias = (const float*)d_in[2];   // [8,256]
    const float* rw   = (const float*)d_in[3];   // [8,256]
    const float* rb   = (const float*)d_in[4];   // [8]
    float* out = (float*)d_out;

    pool_kernel<<<dim3(CIN, NB), 256>>>(x);
    routing_kernel<<<NB, 256>>>(rw, rb, bias);
    aggw_kernel<<<(COUT * CIN * KWT) / 256, 256>>>(wgt);
    conv_kernel<<<dim3(HH / TR, COUT / TOC, NB), 256>>>(x, out);
}

// round 7
// speedup vs baseline: 4.2048x; 4.2048x over previous
#include <cuda_runtime.h>
#include <cuda_fp16.h>
#include <math.h>
#include <stdint.h>

#define NB   16
#define CIN  256
#define COUT 256
#define NE   8
#define HH   64
#define WW   64
#define PXT  4096           // 64*64
#define NK   72             // K chunks: 9 taps * 8 ci-chunks of 32
#define EW   589824         // per-expert weight elems = 256*256*9

// ---------------- scratch (no allocations allowed) ----------------
__device__ float g_pooled[NB * CIN];
__device__ float g_routing[NB * NE];
__device__ float g_aggb[NB * COUT];
// aggregated weights, fp16 hi/lo, layout [b][oc][j][ci]  (ci contiguous)
__device__ __align__(16) __half g_wh[(size_t)NB * COUT * 9 * CIN];
__device__ __align__(16) __half g_wl[(size_t)NB * COUT * 9 * CIN];
// x transposed to [b][px][ci] fp16
__device__ __align__(16) __half g_x[(size_t)NB * PXT * CIN];

__device__ __forceinline__ uint32_t smem_u32(const void* p) {
    uint32_t a;
    asm("{ .reg .u64 t; cvta.to.shared.u64 t, %1; cvt.u32.u64 %0, t; }" : "=r"(a) : "l"(p));
    return a;
}
#define CP_ASYNC16(dst, src) \
    asm volatile("cp.async.cg.shared.global [%0], [%1], 16;" :: "r"(dst), "l"(src))
#define CP_ASYNC16_Z(dst, src, n) \
    asm volatile("cp.async.cg.shared.global [%0], [%1], 16, %2;" :: "r"(dst), "l"(src), "r"(n))
#define CP_COMMIT()  asm volatile("cp.async.commit_group;" ::: "memory")
#define CP_WAIT1()   asm volatile("cp.async.wait_group 1;" ::: "memory")

#define LDSM4(r0, r1, r2, r3, a) \
    asm volatile("ldmatrix.sync.aligned.m8n8.x4.shared.b16 {%0,%1,%2,%3}, [%4];" \
        : "=r"(r0), "=r"(r1), "=r"(r2), "=r"(r3) : "r"(a))

#define MMA16816(d, a, b0v, b1v) \
    asm volatile("mma.sync.aligned.m16n8k16.row.col.f32.f16.f16.f32 " \
        "{%0,%1,%2,%3}, {%4,%5,%6,%7}, {%8,%9}, {%0,%1,%2,%3};" \
        : "+f"((d)[0]), "+f"((d)[1]), "+f"((d)[2]), "+f"((d)[3]) \
        : "r"((a)[0]), "r"((a)[1]), "r"((a)[2]), "r"((a)[3]), "r"(b0v), "r"(b1v))

// ---------------- stage 1: global average pool ----------------
__global__ void pool_kernel(const float* __restrict__ x) {
    int c = blockIdx.x, b = blockIdx.y;
    const float4* p = (const float4*)(x + ((size_t)b * CIN + c) * (HH * WW));
    float s = 0.f;
    for (int i = threadIdx.x; i < (HH * WW) / 4; i += 256) {
        float4 v = p[i];
        s += v.x + v.y + v.z + v.w;
    }
    __shared__ float red[8];
    #pragma unroll
    for (int o = 16; o > 0; o >>= 1) s += __shfl_xor_sync(0xFFFFFFFFu, s, o);
    if ((threadIdx.x & 31) == 0) red[threadIdx.x >> 5] = s;
    __syncthreads();
    if (threadIdx.x == 0) {
        float t = 0.f;
        #pragma unroll
        for (int i = 0; i < 8; i++) t += red[i];
        g_pooled[b * CIN + c] = t * (1.0f / (HH * WW));
    }
}

// ---------------- stage 2: routing + aggregated bias ----------------
__global__ void routing_kernel(const float* __restrict__ rw,
                               const float* __restrict__ rb,
                               const float* __restrict__ bias) {
    int b = blockIdx.x;
    __shared__ float sp[CIN];
    __shared__ float sr[NE];
    sp[threadIdx.x] = g_pooled[b * CIN + threadIdx.x];
    __syncthreads();
    int warp = threadIdx.x >> 5, lane = threadIdx.x & 31;
    if (warp < NE) {
        float s = 0.f;
        for (int c = lane; c < CIN; c += 32) s += sp[c] * rw[warp * CIN + c];
        #pragma unroll
        for (int o = 16; o > 0; o >>= 1) s += __shfl_xor_sync(0xFFFFFFFFu, s, o);
        if (lane == 0) sr[warp] = 1.0f / (1.0f + expf(-(s + rb[warp])));
    }
    __syncthreads();
    if (threadIdx.x < NE) g_routing[b * NE + threadIdx.x] = sr[threadIdx.x];
    float a = 0.f;
    #pragma unroll
    for (int e = 0; e < NE; e++) a += sr[e] * bias[e * COUT + threadIdx.x];
    g_aggb[b * COUT + threadIdx.x] = a;
}

// ---------------- stage 3: aggregate weights -> fp16 hi/lo, [b][oc][j][ci] ----
// one block per oc; reads each expert slice once (coalesced), transposes
// [ci][j] -> [j][ci] through smem per batch (sh indexed by source-linear offset).
__global__ void aggw_kernel(const float* __restrict__ weight) {
    __shared__ float sr[NB * NE];
    __shared__ __half sh[2304];
    __shared__ __half sl[2304];
    int oc = blockIdx.x, t = threadIdx.x;
    if (t < NB * NE) sr[t] = g_routing[t];
    __syncthreads();
    float wv[NE][9];
    const float* wp = weight + (size_t)oc * 2304;
    #pragma unroll
    for (int e = 0; e < NE; e++)
        #pragma unroll
        for (int q = 0; q < 9; q++)
            wv[e][q] = wp[(size_t)e * EW + q * 256 + t];
    for (int b = 0; b < NB; b++) {
        #pragma unroll
        for (int q = 0; q < 9; q++) {
            float a = 0.f;
            #pragma unroll
            for (int e = 0; e < NE; e++) a = fmaf(sr[b * NE + e], wv[e][q], a);
            __half h = __float2half_rn(a);
            __half l = __float2half_rn(a - __half2float(h));
            sh[q * 256 + t] = h;          // staged at source-linear idx = ci*9 + j
            sl[q * 256 + t] = l;
        }
        __syncthreads();
        size_t ob = (((size_t)b * COUT + oc) * 9) * 256;
        #pragma unroll
        for (int q = 0; q < 9; q++) {     // write [j=q][ci=t] from staged [t*9+q]
            g_wh[ob + q * 256 + t] = sh[t * 9 + q];
            g_wl[ob + q * 256 + t] = sl[t * 9 + q];
        }
        __syncthreads();
    }
}

// ---------------- stage 4: x -> [b][px][ci] fp16 (tiled transpose) ----------------
__global__ void xsplit_kernel(const float* __restrict__ x) {
    __shared__ float tile[32][257];
    int pxb = blockIdx.x, cib = blockIdx.y, b = blockIdx.z;
    int t = threadIdx.x;
    int px0 = pxb * 256, ci0 = cib * 32;
    const float* xb = x + ((size_t)b * CIN + ci0) * PXT + px0;
    #pragma unroll 8
    for (int r = 0; r < 32; r++) tile[r][t] = xb[(size_t)r * PXT + t];
    __syncthreads();
    uint32_t hreg[16];
    #pragma unroll
    for (int k = 0; k < 16; k++) {
        __half h0 = __float2half_rn(tile[2 * k][t]);
        __half h1 = __float2half_rn(tile[2 * k + 1][t]);
        hreg[k] = (uint32_t)__half_as_ushort(h0) | ((uint32_t)__half_as_ushort(h1) << 16);
    }
    uint4* dst = (uint4*)(g_x + ((size_t)b * PXT + px0 + t) * CIN + ci0);
    #pragma unroll
    for (int k = 0; k < 4; k++) dst[k] = ((uint4*)hreg)[k];
}

// ---------------- stage 5: fp16 HMMA GEMM (implicit conv), 2-pass hi/lo A ------
// grid (32 px-tiles, 2 oc-tiles, 16 b), 256 thr. CTA tile 128oc x 128px, k-chunk 32.
// smem per stage 24KB (Ah 8K | Al 8K | B 8K), 3 stages, cp.async pipeline.
// Swizzle keyed on (row>>1)&3: even rows {0,2,4,6} and odd rows {1,3,5,7} each get
// 4 distinct 16B chunk slots -> conflict-free ldmatrix (row stride 64B).
#define STG_BYTES 24576
#define SWOFF(row, c) ((uint32_t)(row) * 64u + ((uint32_t)((c) ^ (((row) >> 1) & 3)) << 4))

__global__ __launch_bounds__(256, 2) void gemm_kernel(float* __restrict__ out) {
    extern __shared__ char smem[];
    const uint32_t sbase = smem_u32(smem);
    const int px0 = blockIdx.x * 128;
    const int oc0 = blockIdx.y * 128;
    const int b   = blockIdx.z;
    const int tid = threadIdx.x, wid = tid >> 5, lane = tid & 31;
    const int wm = wid >> 2, wn = wid & 3;          // warp tile: 64oc x 32px

    const __half* wa_h = g_wh + ((size_t)b * COUT + oc0) * 9 * 256;
    const __half* wa_l = g_wl + ((size_t)b * COUT + oc0) * 9 * 256;
    const __half* xb   = g_x + (size_t)b * PXT * CIN;

    // per-thread load geometry: row = tid>>1 (0..127), two 16B chunks c = (tid&1)*2+{0,1}
    const int lrow = tid >> 1;
    const int lc0  = (tid & 1) * 2;

    // B source pixel for this thread's row
    const int p  = px0 + lrow;
    const int pr = p >> 6, pc = p & 63;

    float acc[4][4][4];
    #pragma unroll
    for (int mt = 0; mt < 4; mt++)
        #pragma unroll
        for (int nb = 0; nb < 4; nb++)
            #pragma unroll
            for (int v = 0; v < 4; v++) acc[mt][nb][v] = 0.f;

    // ---- stage loader ----
    auto load_stage = [&](int i, int slot) {
        const int j = i >> 3, ci0 = (i & 7) * 32;
        const int dr = j / 3 - 1, dc = j % 3 - 1;
        const uint32_t sb = sbase + slot * STG_BYTES;
        // A hi / lo
        const __half* ah = wa_h + ((size_t)lrow * 9 + j) * 256 + ci0;
        const __half* al = wa_l + ((size_t)lrow * 9 + j) * 256 + ci0;
        #pragma unroll
        for (int k = 0; k < 2; k++) {
            int c = lc0 + k;
            uint32_t d = SWOFF(lrow, c);
            CP_ASYNC16(sb + d, ah + c * 8);
            CP_ASYNC16(sb + 8192 + d, al + c * 8);
        }
        // B (im2col with zero-fill padding)
        int rr = pr + dr, cc = pc + dc;
        bool ok = ((unsigned)rr < HH) && ((unsigned)cc < WW);
        const __half* bsrc = xb + ((size_t)(ok ? (rr * WW + cc) : 0)) * CIN + ci0;
        uint32_t n = ok ? 16u : 0u;
        #pragma unroll
        for (int k = 0; k < 2; k++) {
            int c = lc0 + k;
            CP_ASYNC16_Z(sb + 16384 + SWOFF(lrow, c), bsrc + c * 8, n);
        }
    };

    load_stage(0, 0); CP_COMMIT();
    load_stage(1, 1); CP_COMMIT();

    for (int i = 0; i < NK; i++) {
        CP_WAIT1();
        __syncthreads();
        if (i + 2 < NK) load_stage(i + 2, (i + 2) % 3);
        CP_COMMIT();

        const uint32_t sb = sbase + (i % 3) * STG_BYTES;
        const uint32_t sA = sb, sAl = sb + 8192, sB = sb + 16384;

        #pragma unroll
        for (int h = 0; h < 2; h++) {          // two k16 halves of the 32-k chunk
            // B fragments: 2x ldmatrix.x4 covering 4 n8 blocks
            uint32_t bf[2][4];
            #pragma unroll
            for (int nbp = 0; nbp < 2; nbp++) {
                int row = wn * 32 + nbp * 16 + ((lane >> 4) << 3) + (lane & 7);
                int c   = h * 2 + ((lane >> 3) & 1);
                LDSM4(bf[nbp][0], bf[nbp][1], bf[nbp][2], bf[nbp][3], sB + SWOFF(row, c));
            }
            // pass over A hi then A lo
            #pragma unroll
            for (int pass = 0; pass < 2; pass++) {
                const uint32_t sAx = pass ? sAl : sA;
                #pragma unroll
                for (int mt = 0; mt < 4; mt++) {
                    uint32_t af[4];
                    int row = wm * 64 + mt * 16 + (lane & 15);
                    int c   = h * 2 + (lane >> 4);
                    LDSM4(af[0], af[1], af[2], af[3], sAx + SWOFF(row, c));
                    MMA16816(acc[mt][0], af, bf[0][0], bf[0][1]);
                    MMA16816(acc[mt][1], af, bf[0][2], bf[0][3]);
                    MMA16816(acc[mt][2], af, bf[1][0], bf[1][1]);
                    MMA16816(acc[mt][3], af, bf[1][2], bf[1][3]);
                }
            }
        }
    }

    // ---- epilogue: + bias, direct gmem stores (float2) ----
    const int r4 = lane >> 2, c2 = (lane & 3) * 2;
    float* ob = out + ((size_t)b * COUT) * PXT;
    #pragma unroll
    for (int mt = 0; mt < 4; mt++) {
        int ocr0 = oc0 + wm * 64 + mt * 16 + r4;
        float bb0 = g_aggb[b * COUT + ocr0];
        float bb1 = g_aggb[b * COUT + ocr0 + 8];
        #pragma unroll
        for (int nb = 0; nb < 4; nb++) {
            int px = px0 + wn * 32 + nb * 8 + c2;
            float2 v0 = make_float2(acc[mt][nb][0] + bb0, acc[mt][nb][1] + bb0);
            float2 v1 = make_float2(acc[mt][nb][2] + bb1, acc[mt][nb][3] + bb1);
            *(float2*)(ob + (size_t)ocr0 * PXT + px) = v0;
            *(float2*)(ob + (size_t)(ocr0 + 8) * PXT + px) = v1;
        }
    }
}

// ---------------- launch ----------------
extern "C" void kernel_launch(void* const* d_in, const int* in_sizes, int n_in,
                              void* d_out, int out_size) {
    const float* x    = (const float*)d_in[0];   // [16,256,64,64]
    const float* wgt  = (const float*)d_in[1];   // [8,256,256,3,3]
    const float* bias = (const float*)d_in[2];   // [8,256]
    const float* rw   = (const float*)d_in[3];   // [8,256]
    const float* rb   = (const float*)d_in[4];   // [8]
    float* out = (float*)d_out;

    cudaFuncSetAttribute(gemm_kernel, cudaFuncAttributeMaxDynamicSharedMemorySize, 3 * STG_BYTES);

    pool_kernel<<<dim3(CIN, NB), 256>>>(x);
    routing_kernel<<<NB, 256>>>(rw, rb, bias);
    aggw_kernel<<<COUT, 256>>>(wgt);
    xsplit_kernel<<<dim3(PXT / 256, CIN / 32, NB), 256>>>(x);
    gemm_kernel<<<dim3(PXT / 128, COUT / 128, NB), 256, 3 * STG_BYTES>>>(out);
}